// round 15
// baseline (speedup 1.0000x reference)
#include <cuda_runtime.h>
#include <cuda_fp16.h>
#include <cstdint>

#define NDMAX 32768
#define EMAX  524288

__device__ float    g_Q[(size_t)NDMAX * 128];
__device__ float    g_qconst[128];
__device__ unsigned g_V16[(size_t)EMAX * 64];          // fp16 V
__device__ float    g_ex[(size_t)EMAX * 8];
__device__ float    g_segsum[NDMAX * 8];
__device__ float    g_agg[(size_t)NDMAX * 128];
// fp16 W image: [chunk(3)][half(2): K/V][128 rows x 272B]
__device__ __align__(16) unsigned char g_Wimg[3 * 2 * 34816];
// fp16 Wout image: 128 rows x 528B
__device__ __align__(16) unsigned char g_WoutImg[128 * 528];
// fp16 Wq[:, :128] hi/lo image: 2 x (128 rows x 272B)
__device__ __align__(16) unsigned char g_WqImg[2 * 34816];

__device__ __forceinline__ uint32_t smem_u32(const void* p) {
    uint32_t a;
    asm("{ .reg .u64 t; cvta.to.shared.u64 t, %1; cvt.u32.u64 %0, t; }" : "=r"(a) : "l"(p));
    return a;
}
__device__ __forceinline__ void ldm_x4(unsigned* r, uint32_t addr) {
    asm volatile("ldmatrix.sync.aligned.m8n8.x4.shared.b16 {%0,%1,%2,%3}, [%4];"
        : "=r"(r[0]), "=r"(r[1]), "=r"(r[2]), "=r"(r[3]) : "r"(addr));
}
__device__ __forceinline__ void mma_f16(float* d, const unsigned* a, const unsigned* b) {
    asm volatile("mma.sync.aligned.m16n8k16.row.col.f32.f16.f16.f32 "
        "{%0,%1,%2,%3}, {%4,%5,%6,%7}, {%8,%9}, {%0,%1,%2,%3};"
        : "+f"(d[0]), "+f"(d[1]), "+f"(d[2]), "+f"(d[3])
        : "r"(a[0]), "r"(a[1]), "r"(a[2]), "r"(a[3]), "r"(b[0]), "r"(b[1]));
}
__device__ __forceinline__ void cp16(uint32_t saddr, const void* g) {
    asm volatile("cp.async.cg.shared.global [%0], [%1], 16;" :: "r"(saddr), "l"(g));
}
#define CP_COMMIT() asm volatile("cp.async.commit_group;" ::: "memory")
#define CP_WAIT0()  asm volatile("cp.async.wait_group 0;" ::: "memory")

// smem layouts (bytes)
// k_kv: A fp16 128x272 (34KB) + B fp16 both halves (68KB); epilogue: Ks 128x136f (68KB) @0, Vs @69632
#define SM_A    0
#define SM_B    34816
#define SM_TOT  139264
#define SMO_B   33792
#define SMO_TOT 101376
#define SMQ_AHI 0
#define SMQ_ALO 17408
#define SMQ_B   34816
#define SMQ_TOT 104448

// ---------------- prep: init + all fp16 weight images + qconst ----------------
__global__ void k_prep(const float* __restrict__ Wk, const float* __restrict__ Wv,
                       const float* __restrict__ Wout,
                       const float* __restrict__ Wq, const float* __restrict__ bq,
                       const float* __restrict__ tb, int Nd) {
    int i = blockIdx.x * 256 + threadIdx.x;
    if (i < Nd * 128) g_agg[i] = 0.f;
    if (i < Nd * 8) g_segsum[i] = 0.f;
    if (i < 98304) {
        int r = i / 384, cg = i % 384;
        float w = (r < 128) ? Wk[(size_t)r * 384 + cg] : Wv[(size_t)(r - 128) * 384 + cg];
        int chunk = cg >> 7, c = cg & 127;
        int half = r >> 7, rr = r & 127;
        size_t base = (size_t)(chunk * 2 + half) * 34816 + (size_t)rr * 272 + c * 2;
        *reinterpret_cast<__half*>(g_Wimg + base) = __float2half_rn(w);
    }
    if (i < 32768) {
        int r = i >> 8, c = i & 255;
        *reinterpret_cast<__half*>(g_WoutImg + (size_t)r * 528 + c * 2) =
            __float2half_rn(Wout[(size_t)r * 256 + c]);
    }
    if (i < 16384) {
        int r = i >> 7, c = i & 127;
        float w = Wq[(size_t)r * 256 + c];
        __half hi = __float2half_rn(w);
        __half lo = __float2half_rn(w - __half2float(hi));
        size_t base = (size_t)r * 272 + c * 2;
        *reinterpret_cast<__half*>(g_WqImg + base) = hi;
        *reinterpret_cast<__half*>(g_WqImg + base + 34816) = lo;
    }
    if (blockIdx.x == 0) {
        __shared__ float ct[128];
        int t = threadIdx.x;
        if (t < 128) ct[t] = cosf(tb[t]);
        __syncthreads();
        if (t < 128) {
            float s = bq[t];
            #pragma unroll 4
            for (int j = 0; j < 128; j++) s += Wq[(size_t)t * 256 + 128 + j] * ct[j];
            g_qconst[t] = s;
        }
    }
}

// ---------------- Q GEMM via mma fp16 3-term split ----------------
__global__ __launch_bounds__(256, 2) void k_qgemm(const float* __restrict__ h, int Nd) {
    extern __shared__ char smg[];
    uint32_t sb = smem_u32(smg);
    int tid = threadIdx.x, lane = tid & 31, wid = tid >> 5;
    int wm = wid >> 2, wn = wid & 3;
    int r0 = blockIdx.x * 64;
    int arow = lane & 15, acolb = (lane >> 4) * 16;
    int bq_row = (lane & 7) + ((lane >> 4) << 3);
    int bq_k = ((lane >> 3) & 1) * 16;

    for (int i = tid; i < 4352; i += 256)
        cp16(sb + SMQ_B + i * 16, reinterpret_cast<const char*>(g_WqImg) + i * 16);
    CP_COMMIT();
    for (int idx = tid; idx < 2048; idx += 256) {
        int r = idx >> 5, c4 = (idx & 31) << 2;
        float4 x = *reinterpret_cast<const float4*>(h + (size_t)(r0 + r) * 128 + c4);
        __half h0 = __float2half_rn(x.x), h1 = __float2half_rn(x.y);
        __half h2 = __float2half_rn(x.z), h3 = __float2half_rn(x.w);
        __half l0 = __float2half_rn(x.x - __half2float(h0));
        __half l1 = __float2half_rn(x.y - __half2float(h1));
        __half l2 = __float2half_rn(x.z - __half2float(h2));
        __half l3 = __float2half_rn(x.w - __half2float(h3));
        uint2 uh, ul;
        uh.x = (uint32_t)__half_as_ushort(h0) | ((uint32_t)__half_as_ushort(h1) << 16);
        uh.y = (uint32_t)__half_as_ushort(h2) | ((uint32_t)__half_as_ushort(h3) << 16);
        ul.x = (uint32_t)__half_as_ushort(l0) | ((uint32_t)__half_as_ushort(l1) << 16);
        ul.y = (uint32_t)__half_as_ushort(l2) | ((uint32_t)__half_as_ushort(l3) << 16);
        uint32_t off = (uint32_t)r * 272 + c4 * 2;
        *reinterpret_cast<uint2*>(smg + SMQ_AHI + off) = uh;
        *reinterpret_cast<uint2*>(smg + SMQ_ALO + off) = ul;
    }
    CP_WAIT0();
    __syncthreads();

    float acc[2][4][4] = {};
    #pragma unroll 2
    for (int k16 = 0; k16 < 8; k16++) {
        int kb = k16 * 32;
        unsigned ahi[2][4], alo[2][4];
        #pragma unroll
        for (int mi = 0; mi < 2; mi++) {
            uint32_t ad = sb + (uint32_t)(wm * 32 + mi * 16 + arow) * 272 + kb + acolb;
            ldm_x4(ahi[mi], ad + SMQ_AHI);
            ldm_x4(alo[mi], ad + SMQ_ALO);
        }
        #pragma unroll
        for (int p = 0; p < 2; p++) {
            unsigned bhi[4], blo[4];
            uint32_t bd = sb + SMQ_B + (uint32_t)(wn * 32 + p * 16 + bq_row) * 272 + kb + bq_k;
            ldm_x4(bhi, bd);
            ldm_x4(blo, bd + 34816);
            #pragma unroll
            for (int mi = 0; mi < 2; mi++) {
                mma_f16(acc[mi][2 * p],     ahi[mi], bhi);
                mma_f16(acc[mi][2 * p],     ahi[mi], blo);
                mma_f16(acc[mi][2 * p],     alo[mi], bhi);
                mma_f16(acc[mi][2 * p + 1], ahi[mi], bhi + 2);
                mma_f16(acc[mi][2 * p + 1], ahi[mi], blo + 2);
                mma_f16(acc[mi][2 * p + 1], alo[mi], bhi + 2);
            }
        }
    }
    __syncthreads();

    float* Stg = reinterpret_cast<float*>(smg);
    #pragma unroll
    for (int mi = 0; mi < 2; mi++) {
        int r = wm * 32 + mi * 16 + (lane >> 2);
        #pragma unroll
        for (int ni = 0; ni < 4; ni++) {
            int c = wn * 32 + ni * 8 + (lane & 3) * 2;
            Stg[r * 136 + c]           = acc[mi][ni][0];
            Stg[r * 136 + c + 1]       = acc[mi][ni][1];
            Stg[(r + 8) * 136 + c]     = acc[mi][ni][2];
            Stg[(r + 8) * 136 + c + 1] = acc[mi][ni][3];
        }
    }
    __syncthreads();
    for (int idx = tid; idx < 2048; idx += 256) {
        int r = idx >> 5, c4 = (idx & 31) << 2;
        float4 v = *reinterpret_cast<const float4*>(Stg + r * 136 + c4);
        v.x += g_qconst[c4 + 0]; v.y += g_qconst[c4 + 1];
        v.z += g_qconst[c4 + 2]; v.w += g_qconst[c4 + 3];
        *reinterpret_cast<float4*>(g_Q + (size_t)(r0 + r) * 128 + c4) = v;
    }
}

// ---------------- KV GEMM: fp16 1-term, 128 edges/block, 512 thr, 1 CTA/SM ----------------
// 16 warps: wm = wid>>2 (4 x 32 edges), wn = wid&3 (4 x 64 outs across K||V)
__global__ __launch_bounds__(512, 1) void k_kv(
    const float* __restrict__ h, const float* __restrict__ f,
    const float* __restrict__ dt, const int* __restrict__ dst,
    const float* __restrict__ freq, const float* __restrict__ tb,
    const float* __restrict__ bk, const float* __restrict__ bv,
    int Nd, int E)
{
    extern __shared__ char smc[];
    uint32_t sb = smem_u32(smc);
    int tid = threadIdx.x, lane = tid & 31, wid = tid >> 5;
    int wm = wid >> 2, wn = wid & 3;
    int e0 = blockIdx.x * 128;

    int arow = lane & 15, acolb = (lane >> 4) * 16;
    int bq_row = (lane & 7) + ((lane >> 4) << 3);
    int bq_k = ((lane >> 3) & 1) * 16;

    uint32_t bwbase = sb + SM_B + (uint32_t)(wn >> 1) * 34816 + (uint32_t)((wn & 1) * 64) * 272;

    float acc[2][8][4] = {};

    for (int chunk = 0; chunk < 3; chunk++) {
        __syncthreads();
        {
            const char* src = reinterpret_cast<const char*>(g_Wimg) + (size_t)chunk * 69632;
            for (int i = tid; i < 4352; i += 512)
                cp16(sb + SM_B + i * 16, src + i * 16);
            CP_COMMIT();
        }
        for (int idx = tid; idx < 4096; idx += 512) {
            int e = idx >> 5, k4 = (idx & 31) << 2;
            float4 x;
            if (chunk == 0) {
                x = *reinterpret_cast<const float4*>(h + (size_t)(Nd + e0 + e) * 128 + k4);
            } else if (chunk == 1) {
                x = *reinterpret_cast<const float4*>(f + (size_t)(e0 + e) * 128 + k4);
            } else {
                float dtv = dt[e0 + e];
                x.x = __cosf(fmaf(dtv, freq[k4 + 0], tb[k4 + 0]));
                x.y = __cosf(fmaf(dtv, freq[k4 + 1], tb[k4 + 1]));
                x.z = __cosf(fmaf(dtv, freq[k4 + 2], tb[k4 + 2]));
                x.w = __cosf(fmaf(dtv, freq[k4 + 3], tb[k4 + 3]));
            }
            __half2 p0 = __floats2half2_rn(x.x, x.y);
            __half2 p1 = __floats2half2_rn(x.z, x.w);
            uint2 uh;
            uh.x = *reinterpret_cast<unsigned*>(&p0);
            uh.y = *reinterpret_cast<unsigned*>(&p1);
            uint32_t off = (uint32_t)e * 272 + k4 * 2;
            *reinterpret_cast<uint2*>(smc + SM_A + off) = uh;
        }
        CP_WAIT0();
        __syncthreads();

        #pragma unroll 2
        for (int k16 = 0; k16 < 8; k16++) {
            int kb = k16 * 32;
            unsigned a4[2][4];
            #pragma unroll
            for (int mi = 0; mi < 2; mi++) {
                uint32_t ad = sb + SM_A + (uint32_t)(wm * 32 + mi * 16 + arow) * 272 + kb + acolb;
                ldm_x4(a4[mi], ad);
            }
            #pragma unroll
            for (int p = 0; p < 4; p++) {
                unsigned b4[4];
                uint32_t bd = bwbase + (uint32_t)(p * 16 + bq_row) * 272 + kb + bq_k;
                ldm_x4(b4, bd);
                #pragma unroll
                for (int mi = 0; mi < 2; mi++) {
                    mma_f16(acc[mi][2 * p],     a4[mi], b4);
                    mma_f16(acc[mi][2 * p + 1], a4[mi], b4 + 2);
                }
            }
        }
    }
    __syncthreads();

    float* Ks = reinterpret_cast<float*>(smc);            // 128 x 136 floats
    float* Vs = reinterpret_cast<float*>(smc + 69632);    // 128 x 136 floats
    {
        float* stage = (wn < 2) ? Ks : Vs;
        const float* bias = (wn < 2) ? bk : bv;
        int cbase = (wn & 1) * 64;
        #pragma unroll
        for (int mi = 0; mi < 2; mi++) {
            int r = wm * 32 + mi * 16 + (lane >> 2);
            #pragma unroll
            for (int ni = 0; ni < 8; ni++) {
                int c = cbase + ni * 8 + (lane & 3) * 2;
                float b0 = bias[c], b1 = bias[c + 1];
                stage[r * 136 + c]           = acc[mi][ni][0] + b0;
                stage[r * 136 + c + 1]       = acc[mi][ni][1] + b1;
                stage[(r + 8) * 136 + c]     = acc[mi][ni][2] + b0;
                stage[(r + 8) * 136 + c + 1] = acc[mi][ni][3] + b1;
            }
        }
    }
    __syncthreads();

    for (int t = tid; t < 1024; t += 512) {
        int e = t >> 3, hh = t & 7;
        int d = dst[e0 + e];
        const float4* qp = reinterpret_cast<const float4*>(g_Q + (size_t)d * 128 + hh * 16);
        const float4* kp = reinterpret_cast<const float4*>(Ks + e * 136 + hh * 16);
        float s = 0.f;
        #pragma unroll
        for (int u = 0; u < 4; u++) {
            float4 q = qp[u], kv = kp[u];
            s += q.x * kv.x + q.y * kv.y + q.z * kv.z + q.w * kv.w;
        }
        float lg = (s >= 0.f) ? s : 0.2f * s;
        float ex = __expf(fminf(lg, 60.f));
        g_ex[(size_t)(e0 + e) * 8 + hh] = ex;
        atomicAdd(&g_segsum[d * 8 + hh], ex);
    }
    for (int idx = tid; idx < 4096; idx += 512) {
        int e = idx >> 5, u2 = idx & 31;
        const float4 v = *reinterpret_cast<const float4*>(Vs + e * 136 + u2 * 4);
        __half2 p0 = __floats2half2_rn(v.x, v.y);
        __half2 p1 = __floats2half2_rn(v.z, v.w);
        uint2 uo;
        uo.x = *reinterpret_cast<const unsigned*>(&p0);
        uo.y = *reinterpret_cast<const unsigned*>(&p1);
        *reinterpret_cast<uint2*>(g_V16 + (size_t)(e0 + e) * 64 + u2 * 2) = uo;
    }
}

// ---------------- pass3: 4 edges per warp, no shuffle ----------------
__global__ __launch_bounds__(256) void k_pass3(const int* __restrict__ dst, int E) {
    int tid = threadIdx.x, lane = tid & 31, wid = tid >> 5;
    int ebase = blockIdx.x * 32 + wid;
    int hh = lane >> 2;
    #pragma unroll
    for (int rep = 0; rep < 4; rep++) {
        int e = ebase + rep * 8;
        int d = dst[e];
        float att = __fdividef(g_ex[(size_t)e * 8 + hh], g_segsum[d * 8 + hh]);
        uint2 v2 = *reinterpret_cast<const uint2*>(g_V16 + (size_t)e * 64 + lane * 2);
        __half2 p0 = *reinterpret_cast<__half2*>(&v2.x);
        __half2 p1 = *reinterpret_cast<__half2*>(&v2.y);
        float2 f0 = __half22float2(p0), f1 = __half22float2(p1);
        float* ap = g_agg + (size_t)d * 128 + lane * 4;
        asm volatile("red.global.add.v4.f32 [%0], {%1, %2, %3, %4};"
            :: "l"(ap), "f"(f0.x * att), "f"(f0.y * att), "f"(f1.x * att), "f"(f1.y * att)
            : "memory");
    }
}

// ---------------- out GEMM via mma fp16 + fused LN ----------------
__global__ __launch_bounds__(256, 2) void k_out(
    const float* __restrict__ h, const float* __restrict__ bout,
    const float* __restrict__ gamma, const float* __restrict__ beta,
    float* __restrict__ out, int Nd)
{
    extern __shared__ char smo[];
    uint32_t sb = smem_u32(smo);
    int tid = threadIdx.x, lane = tid & 31, wid = tid >> 5;
    int wm = wid >> 2, wn = wid & 3;
    int r0 = blockIdx.x * 64;

    int arow = lane & 15, acolb = (lane >> 4) * 16;
    int brow = lane & 7,  bcolb = ((lane >> 3) & 1) * 16;

    for (int i = tid; i < 4224; i += 256)
        cp16(sb + SMO_B + i * 16, reinterpret_cast<const char*>(g_WoutImg) + i * 16);
    CP_COMMIT();
    for (int idx = tid; idx < 4096; idx += 256) {
        int r = idx >> 6, c4 = (idx & 63) << 2;
        float4 x;
        if (c4 < 128) x = *reinterpret_cast<const float4*>(g_agg + (size_t)(r0 + r) * 128 + c4);
        else          x = *reinterpret_cast<const float4*>(h + (size_t)(r0 + r) * 128 + (c4 - 128));
        __half2 p0 = __floats2half2_rn(x.x, x.y);
        __half2 p1 = __floats2half2_rn(x.z, x.w);
        uint2 uh;
        uh.x = *reinterpret_cast<unsigned*>(&p0);
        uh.y = *reinterpret_cast<unsigned*>(&p1);
        *reinterpret_cast<uint2*>(smo + (uint32_t)r * 528 + c4 * 2) = uh;
    }
    CP_WAIT0();
    __syncthreads();

    float acc[2][4][4] = {};
    #pragma unroll 2
    for (int k16 = 0; k16 < 16; k16++) {
        int kb = k16 * 32;
        unsigned a4[2][4];
        #pragma unroll
        for (int mi = 0; mi < 2; mi++) {
            uint32_t ad = sb + (uint32_t)(wm * 32 + mi * 16 + arow) * 528 + kb + acolb;
            ldm_x4(a4[mi], ad);
        }
        #pragma unroll
        for (int ni = 0; ni < 4; ni++) {
            unsigned b2[2];
            uint32_t bd = sb + SMO_B + (uint32_t)(wn * 32 + ni * 8 + brow) * 528 + kb + bcolb;
            asm volatile("ldmatrix.sync.aligned.m8n8.x2.shared.b16 {%0,%1}, [%2];"
                : "=r"(b2[0]), "=r"(b2[1]) : "r"(bd));
            #pragma unroll
            for (int mi = 0; mi < 2; mi++)
                mma_f16(acc[mi][ni], a4[mi], b2);
        }
    }
    __syncthreads();

    float* Stg = reinterpret_cast<float*>(smo);
    #pragma unroll
    for (int mi = 0; mi < 2; mi++) {
        int r = wm * 32 + mi * 16 + (lane >> 2);
        #pragma unroll
        for (int ni = 0; ni < 4; ni++) {
            int c = wn * 32 + ni * 8 + (lane & 3) * 2;
            float b0 = bout[c], b1 = bout[c + 1];
            float v0 = acc[mi][ni][0] + b0, v1 = acc[mi][ni][1] + b1;
            float v2 = acc[mi][ni][2] + b0, v3 = acc[mi][ni][3] + b1;
            Stg[r * 136 + c]           = v0 > 0.f ? v0 : 0.f;
            Stg[r * 136 + c + 1]       = v1 > 0.f ? v1 : 0.f;
            Stg[(r + 8) * 136 + c]     = v2 > 0.f ? v2 : 0.f;
            Stg[(r + 8) * 136 + c + 1] = v3 > 0.f ? v3 : 0.f;
        }
    }
    __syncthreads();

    {
        int r = tid >> 2, q = tid & 3;
        float vals[32];
        float rsum = 0.f, rsq = 0.f;
        const float4* sp = reinterpret_cast<const float4*>(Stg + r * 136 + q * 32);
        #pragma unroll
        for (int u = 0; u < 8; u++) {
            float4 v = sp[u];
            vals[u * 4 + 0] = v.x; vals[u * 4 + 1] = v.y;
            vals[u * 4 + 2] = v.z; vals[u * 4 + 3] = v.w;
            rsum += v.x + v.y + v.z + v.w;
            rsq  += v.x * v.x + v.y * v.y + v.z * v.z + v.w * v.w;
        }
        #pragma unroll
        for (int m = 1; m <= 2; m <<= 1) {
            rsum += __shfl_xor_sync(0xffffffffu, rsum, m);
            rsq  += __shfl_xor_sync(0xffffffffu, rsq, m);
        }
        float mu = rsum * (1.f / 128.f);
        float var = rsq * (1.f / 128.f) - mu * mu;
        float inv = rsqrtf(var + 1e-5f);
        float* op = out + (size_t)(r0 + r) * 128 + q * 32;
        #pragma unroll
        for (int i = 0; i < 32; i++) {
            int col = q * 32 + i;
            op[i] = (vals[i] - mu) * inv * gamma[col] + beta[col];
        }
    }
}

extern "C" void kernel_launch(void* const* d_in, const int* in_sizes, int n_in,
                              void* d_out, int out_size) {
    const float* h    = (const float*)d_in[0];
    const float* f    = (const float*)d_in[1];
    const float* dt   = (const float*)d_in[2];
    const int*   dst  = (const int*)  d_in[3];
    const float* freq = (const float*)d_in[4];
    const float* tb   = (const float*)d_in[5];
    const float* Wq   = (const float*)d_in[6];
    const float* bq   = (const float*)d_in[7];
    const float* Wk   = (const float*)d_in[8];
    const float* bk   = (const float*)d_in[9];
    const float* Wv   = (const float*)d_in[10];
    const float* bv   = (const float*)d_in[11];
    const float* Wout = (const float*)d_in[12];
    const float* bout = (const float*)d_in[13];
    const float* gam  = (const float*)d_in[14];
    const float* bet  = (const float*)d_in[15];
    float* out = (float*)d_out;

    int E  = in_sizes[2];
    int Nd = in_sizes[0] / 128 - E;

    cudaFuncSetAttribute(k_qgemm, cudaFuncAttributeMaxDynamicSharedMemorySize, SMQ_TOT);
    cudaFuncSetAttribute(k_kv,    cudaFuncAttributeMaxDynamicSharedMemorySize, SM_TOT);
    cudaFuncSetAttribute(k_out,   cudaFuncAttributeMaxDynamicSharedMemorySize, SMO_TOT);

    k_prep<<<(Nd * 128 + 255) / 256, 256>>>(Wk, Wv, Wout, Wq, bq, tb, Nd);
    k_qgemm<<<Nd / 64, 256, SMQ_TOT>>>(h, Nd);
    k_kv<<<E / 128, 512, SM_TOT>>>(h, f, dt, dst, freq, tb, bk, bv, Nd, E);
    k_pass3<<<E / 32, 256>>>(dst, E);
    k_out<<<Nd / 64, 256, SMO_TOT>>>(h, bout, gam, bet, out, Nd);
}

// round 16
// speedup vs baseline: 1.1251x; 1.1251x over previous
#include <cuda_runtime.h>
#include <cuda_fp16.h>
#include <cstdint>

#define NDMAX 32768
#define EMAX  524288

__device__ float    g_Q[(size_t)NDMAX * 128];
__device__ float    g_qconst[128];
__device__ unsigned g_V16[(size_t)EMAX * 64];          // fp16 V
__device__ float    g_ex[(size_t)EMAX * 8];
__device__ float    g_segsum[NDMAX * 8];
__device__ float    g_agg[(size_t)NDMAX * 128];
// fp16 W image: [chunk(3)][half(2): K/V][128 rows x 272B]
__device__ __align__(16) unsigned char g_Wimg[3 * 2 * 34816];
// fp16 Wout image: 128 rows x 528B
__device__ __align__(16) unsigned char g_WoutImg[128 * 528];
// fp16 Wq[:, :128] hi/lo image: 2 x (128 rows x 272B)
__device__ __align__(16) unsigned char g_WqImg[2 * 34816];

__device__ __forceinline__ uint32_t smem_u32(const void* p) {
    uint32_t a;
    asm("{ .reg .u64 t; cvta.to.shared.u64 t, %1; cvt.u32.u64 %0, t; }" : "=r"(a) : "l"(p));
    return a;
}
__device__ __forceinline__ void ldm_x4(unsigned* r, uint32_t addr) {
    asm volatile("ldmatrix.sync.aligned.m8n8.x4.shared.b16 {%0,%1,%2,%3}, [%4];"
        : "=r"(r[0]), "=r"(r[1]), "=r"(r[2]), "=r"(r[3]) : "r"(addr));
}
__device__ __forceinline__ void mma_f16(float* d, const unsigned* a, const unsigned* b) {
    asm volatile("mma.sync.aligned.m16n8k16.row.col.f32.f16.f16.f32 "
        "{%0,%1,%2,%3}, {%4,%5,%6,%7}, {%8,%9}, {%0,%1,%2,%3};"
        : "+f"(d[0]), "+f"(d[1]), "+f"(d[2]), "+f"(d[3])
        : "r"(a[0]), "r"(a[1]), "r"(a[2]), "r"(a[3]), "r"(b[0]), "r"(b[1]));
}
__device__ __forceinline__ void cp16(uint32_t saddr, const void* g) {
    asm volatile("cp.async.cg.shared.global [%0], [%1], 16;" :: "r"(saddr), "l"(g));
}
#define CP_COMMIT() asm volatile("cp.async.commit_group;" ::: "memory")
#define CP_WAIT0()  asm volatile("cp.async.wait_group 0;" ::: "memory")

// smem layouts (bytes)
#define SM_A    0
#define SM_B    17408
#define SM_TOT  87040
#define SMO_B   33792
#define SMO_TOT 101376
#define SMQ_AHI 0
#define SMQ_ALO 17408
#define SMQ_B   34816
#define SMQ_TOT 104448

// ---------------- prep: init + all fp16 weight images + qconst ----------------
__global__ void k_prep(const float* __restrict__ Wk, const float* __restrict__ Wv,
                       const float* __restrict__ Wout,
                       const float* __restrict__ Wq, const float* __restrict__ bq,
                       const float* __restrict__ tb, int Nd) {
    int i = blockIdx.x * 256 + threadIdx.x;
    if (i < Nd * 128) g_agg[i] = 0.f;
    if (i < Nd * 8) g_segsum[i] = 0.f;
    if (i < 98304) {
        int r = i / 384, cg = i % 384;
        float w = (r < 128) ? Wk[(size_t)r * 384 + cg] : Wv[(size_t)(r - 128) * 384 + cg];
        int chunk = cg >> 7, c = cg & 127;
        int half = r >> 7, rr = r & 127;
        size_t base = (size_t)(chunk * 2 + half) * 34816 + (size_t)rr * 272 + c * 2;
        *reinterpret_cast<__half*>(g_Wimg + base) = __float2half_rn(w);
    }
    if (i < 32768) {
        int r = i >> 8, c = i & 255;
        *reinterpret_cast<__half*>(g_WoutImg + (size_t)r * 528 + c * 2) =
            __float2half_rn(Wout[(size_t)r * 256 + c]);
    }
    if (i < 16384) {
        int r = i >> 7, c = i & 127;
        float w = Wq[(size_t)r * 256 + c];
        __half hi = __float2half_rn(w);
        __half lo = __float2half_rn(w - __half2float(hi));
        size_t base = (size_t)r * 272 + c * 2;
        *reinterpret_cast<__half*>(g_WqImg + base) = hi;
        *reinterpret_cast<__half*>(g_WqImg + base + 34816) = lo;
    }
    if (blockIdx.x == 0) {
        __shared__ float ct[128];
        int t = threadIdx.x;
        if (t < 128) ct[t] = cosf(tb[t]);
        __syncthreads();
        if (t < 128) {
            float s = bq[t];
            #pragma unroll 4
            for (int j = 0; j < 128; j++) s += Wq[(size_t)t * 256 + 128 + j] * ct[j];
            g_qconst[t] = s;
        }
    }
}

// ---------------- Q GEMM via mma fp16 3-term split ----------------
__global__ __launch_bounds__(256, 2) void k_qgemm(const float* __restrict__ h, int Nd) {
    extern __shared__ char smg[];
    uint32_t sb = smem_u32(smg);
    int tid = threadIdx.x, lane = tid & 31, wid = tid >> 5;
    int wm = wid >> 2, wn = wid & 3;
    int r0 = blockIdx.x * 64;
    int arow = lane & 15, acolb = (lane >> 4) * 16;
    int bq_row = (lane & 7) + ((lane >> 4) << 3);
    int bq_k = ((lane >> 3) & 1) * 16;

    for (int i = tid; i < 4352; i += 256)
        cp16(sb + SMQ_B + i * 16, reinterpret_cast<const char*>(g_WqImg) + i * 16);
    CP_COMMIT();
    for (int idx = tid; idx < 2048; idx += 256) {
        int r = idx >> 5, c4 = (idx & 31) << 2;
        float4 x = *reinterpret_cast<const float4*>(h + (size_t)(r0 + r) * 128 + c4);
        __half h0 = __float2half_rn(x.x), h1 = __float2half_rn(x.y);
        __half h2 = __float2half_rn(x.z), h3 = __float2half_rn(x.w);
        __half l0 = __float2half_rn(x.x - __half2float(h0));
        __half l1 = __float2half_rn(x.y - __half2float(h1));
        __half l2 = __float2half_rn(x.z - __half2float(h2));
        __half l3 = __float2half_rn(x.w - __half2float(h3));
        uint2 uh, ul;
        uh.x = (uint32_t)__half_as_ushort(h0) | ((uint32_t)__half_as_ushort(h1) << 16);
        uh.y = (uint32_t)__half_as_ushort(h2) | ((uint32_t)__half_as_ushort(h3) << 16);
        ul.x = (uint32_t)__half_as_ushort(l0) | ((uint32_t)__half_as_ushort(l1) << 16);
        ul.y = (uint32_t)__half_as_ushort(l2) | ((uint32_t)__half_as_ushort(l3) << 16);
        uint32_t off = (uint32_t)r * 272 + c4 * 2;
        *reinterpret_cast<uint2*>(smg + SMQ_AHI + off) = uh;
        *reinterpret_cast<uint2*>(smg + SMQ_ALO + off) = ul;
    }
    CP_WAIT0();
    __syncthreads();

    float acc[2][4][4] = {};
    #pragma unroll 2
    for (int k16 = 0; k16 < 8; k16++) {
        int kb = k16 * 32;
        unsigned ahi[2][4], alo[2][4];
        #pragma unroll
        for (int mi = 0; mi < 2; mi++) {
            uint32_t ad = sb + (uint32_t)(wm * 32 + mi * 16 + arow) * 272 + kb + acolb;
            ldm_x4(ahi[mi], ad + SMQ_AHI);
            ldm_x4(alo[mi], ad + SMQ_ALO);
        }
        #pragma unroll
        for (int p = 0; p < 2; p++) {
            unsigned bhi[4], blo[4];
            uint32_t bd = sb + SMQ_B + (uint32_t)(wn * 32 + p * 16 + bq_row) * 272 + kb + bq_k;
            ldm_x4(bhi, bd);
            ldm_x4(blo, bd + 34816);
            #pragma unroll
            for (int mi = 0; mi < 2; mi++) {
                mma_f16(acc[mi][2 * p],     ahi[mi], bhi);
                mma_f16(acc[mi][2 * p],     ahi[mi], blo);
                mma_f16(acc[mi][2 * p],     alo[mi], bhi);
                mma_f16(acc[mi][2 * p + 1], ahi[mi], bhi + 2);
                mma_f16(acc[mi][2 * p + 1], ahi[mi], blo + 2);
                mma_f16(acc[mi][2 * p + 1], alo[mi], bhi + 2);
            }
        }
    }
    __syncthreads();

    float* Stg = reinterpret_cast<float*>(smg);
    #pragma unroll
    for (int mi = 0; mi < 2; mi++) {
        int r = wm * 32 + mi * 16 + (lane >> 2);
        #pragma unroll
        for (int ni = 0; ni < 4; ni++) {
            int c = wn * 32 + ni * 8 + (lane & 3) * 2;
            Stg[r * 136 + c]           = acc[mi][ni][0];
            Stg[r * 136 + c + 1]       = acc[mi][ni][1];
            Stg[(r + 8) * 136 + c]     = acc[mi][ni][2];
            Stg[(r + 8) * 136 + c + 1] = acc[mi][ni][3];
        }
    }
    __syncthreads();
    for (int idx = tid; idx < 2048; idx += 256) {
        int r = idx >> 5, c4 = (idx & 31) << 2;
        float4 v = *reinterpret_cast<const float4*>(Stg + r * 136 + c4);
        v.x += g_qconst[c4 + 0]; v.y += g_qconst[c4 + 1];
        v.z += g_qconst[c4 + 2]; v.w += g_qconst[c4 + 3];
        *reinterpret_cast<float4*>(g_Q + (size_t)(r0 + r) * 128 + c4) = v;
    }
}

// ---------------- KV GEMM: plain fp16 1-term, 64 edges/block, 256 thr, 2 CTAs/SM ----------------
__global__ __launch_bounds__(256, 2) void k_kv(
    const float* __restrict__ h, const float* __restrict__ f,
    const float* __restrict__ dt, const int* __restrict__ dst,
    const float* __restrict__ freq, const float* __restrict__ tb,
    const float* __restrict__ bk, const float* __restrict__ bv,
    int Nd, int E)
{
    extern __shared__ char smc[];
    uint32_t sb = smem_u32(smc);
    int tid = threadIdx.x, lane = tid & 31, wid = tid >> 5;
    int wm = wid >> 2, wn = wid & 3;
    int e0 = blockIdx.x * 64;

    int arow = lane & 15, acolb = (lane >> 4) * 16;
    int bq_row = (lane & 7) + ((lane >> 4) << 3);
    int bq_k = ((lane >> 3) & 1) * 16;

    uint32_t bwbase = sb + SM_B + (uint32_t)(wn >> 1) * 34816 + (uint32_t)((wn & 1) * 64) * 272;

    float acc[2][8][4] = {};

    for (int chunk = 0; chunk < 3; chunk++) {
        __syncthreads();
        {
            const char* src = reinterpret_cast<const char*>(g_Wimg) + (size_t)chunk * 69632;
            for (int i = tid; i < 4352; i += 256)
                cp16(sb + SM_B + i * 16, src + i * 16);
            CP_COMMIT();
        }
        for (int idx = tid; idx < 2048; idx += 256) {
            int e = idx >> 5, k4 = (idx & 31) << 2;
            float4 x;
            if (chunk == 0) {
                x = *reinterpret_cast<const float4*>(h + (size_t)(Nd + e0 + e) * 128 + k4);
            } else if (chunk == 1) {
                x = *reinterpret_cast<const float4*>(f + (size_t)(e0 + e) * 128 + k4);
            } else {
                float dtv = dt[e0 + e];
                x.x = __cosf(fmaf(dtv, freq[k4 + 0], tb[k4 + 0]));
                x.y = __cosf(fmaf(dtv, freq[k4 + 1], tb[k4 + 1]));
                x.z = __cosf(fmaf(dtv, freq[k4 + 2], tb[k4 + 2]));
                x.w = __cosf(fmaf(dtv, freq[k4 + 3], tb[k4 + 3]));
            }
            __half2 p0 = __floats2half2_rn(x.x, x.y);
            __half2 p1 = __floats2half2_rn(x.z, x.w);
            uint2 uh;
            uh.x = *reinterpret_cast<unsigned*>(&p0);
            uh.y = *reinterpret_cast<unsigned*>(&p1);
            uint32_t off = (uint32_t)e * 272 + k4 * 2;
            *reinterpret_cast<uint2*>(smc + SM_A + off) = uh;
        }
        CP_WAIT0();
        __syncthreads();

        #pragma unroll 2
        for (int k16 = 0; k16 < 8; k16++) {
            int kb = k16 * 32;
            unsigned a4[2][4];
            #pragma unroll
            for (int mi = 0; mi < 2; mi++) {
                uint32_t ad = sb + SM_A + (uint32_t)(wm * 32 + mi * 16 + arow) * 272 + kb + acolb;
                ldm_x4(a4[mi], ad);
            }
            #pragma unroll
            for (int p = 0; p < 4; p++) {
                unsigned b4[4];
                uint32_t bd = bwbase + (uint32_t)(p * 16 + bq_row) * 272 + kb + bq_k;
                ldm_x4(b4, bd);
                #pragma unroll
                for (int mi = 0; mi < 2; mi++) {
                    mma_f16(acc[mi][2 * p],     a4[mi], b4);
                    mma_f16(acc[mi][2 * p + 1], a4[mi], b4 + 2);
                }
            }
        }
    }
    __syncthreads();

    float* Ks = reinterpret_cast<float*>(smc);
    float* Vs = reinterpret_cast<float*>(smc + 34816);
    {
        float* stage = (wn < 2) ? Ks : Vs;
        const float* bias = (wn < 2) ? bk : bv;
        int cbase = (wn & 1) * 64;
        #pragma unroll
        for (int mi = 0; mi < 2; mi++) {
            int r = wm * 32 + mi * 16 + (lane >> 2);
            #pragma unroll
            for (int ni = 0; ni < 8; ni++) {
                int c = cbase + ni * 8 + (lane & 3) * 2;
                float b0 = bias[c], b1 = bias[c + 1];
                stage[r * 136 + c]           = acc[mi][ni][0] + b0;
                stage[r * 136 + c + 1]       = acc[mi][ni][1] + b1;
                stage[(r + 8) * 136 + c]     = acc[mi][ni][2] + b0;
                stage[(r + 8) * 136 + c + 1] = acc[mi][ni][3] + b1;
            }
        }
    }
    __syncthreads();

    for (int t = tid; t < 512; t += 256) {
        int e = t >> 3, hh = t & 7;
        int d = dst[e0 + e];
        const float4* qp = reinterpret_cast<const float4*>(g_Q + (size_t)d * 128 + hh * 16);
        const float4* kp = reinterpret_cast<const float4*>(Ks + e * 136 + hh * 16);
        float s = 0.f;
        #pragma unroll
        for (int u = 0; u < 4; u++) {
            float4 q = qp[u], kv = kp[u];
            s += q.x * kv.x + q.y * kv.y + q.z * kv.z + q.w * kv.w;
        }
        float lg = (s >= 0.f) ? s : 0.2f * s;
        float ex = __expf(fminf(lg, 60.f));
        g_ex[(size_t)(e0 + e) * 8 + hh] = ex;
        atomicAdd(&g_segsum[d * 8 + hh], ex);
    }
    for (int idx = tid; idx < 2048; idx += 256) {
        int e = idx >> 5, u2 = idx & 31;
        const float4 v = *reinterpret_cast<const float4*>(Vs + e * 136 + u2 * 4);
        __half2 p0 = __floats2half2_rn(v.x, v.y);
        __half2 p1 = __floats2half2_rn(v.z, v.w);
        uint2 uo;
        uo.x = *reinterpret_cast<const unsigned*>(&p0);
        uo.y = *reinterpret_cast<const unsigned*>(&p1);
        *reinterpret_cast<uint2*>(g_V16 + (size_t)(e0 + e) * 64 + u2 * 2) = uo;
    }
}

// ---------------- pass3: 4 contiguous edges per warp, int4 dst load ----------------
__global__ __launch_bounds__(256) void k_pass3(const int* __restrict__ dst, int E) {
    int tid = threadIdx.x, lane = tid & 31, wid = tid >> 5;
    int e0 = blockIdx.x * 32 + wid * 4;
    int hh = lane >> 2;
    int4 d4 = *reinterpret_cast<const int4*>(dst + e0);
    int ds[4] = {d4.x, d4.y, d4.z, d4.w};
    #pragma unroll
    for (int rep = 0; rep < 4; rep++) {
        int e = e0 + rep;
        int d = ds[rep];
        float att = __fdividef(g_ex[(size_t)e * 8 + hh], g_segsum[d * 8 + hh]);
        uint2 v2 = *reinterpret_cast<const uint2*>(g_V16 + (size_t)e * 64 + lane * 2);
        __half2 p0 = *reinterpret_cast<__half2*>(&v2.x);
        __half2 p1 = *reinterpret_cast<__half2*>(&v2.y);
        float2 f0 = __half22float2(p0), f1 = __half22float2(p1);
        float* ap = g_agg + (size_t)d * 128 + lane * 4;
        asm volatile("red.global.add.v4.f32 [%0], {%1, %2, %3, %4};"
            :: "l"(ap), "f"(f0.x * att), "f"(f0.y * att), "f"(f1.x * att), "f"(f1.y * att)
            : "memory");
    }
}

// ---------------- out GEMM via mma fp16 + fused LN ----------------
__global__ __launch_bounds__(256, 2) void k_out(
    const float* __restrict__ h, const float* __restrict__ bout,
    const float* __restrict__ gamma, const float* __restrict__ beta,
    float* __restrict__ out, int Nd)
{
    extern __shared__ char smo[];
    uint32_t sb = smem_u32(smo);
    int tid = threadIdx.x, lane = tid & 31, wid = tid >> 5;
    int wm = wid >> 2, wn = wid & 3;
    int r0 = blockIdx.x * 64;

    int arow = lane & 15, acolb = (lane >> 4) * 16;
    int brow = lane & 7,  bcolb = ((lane >> 3) & 1) * 16;

    for (int i = tid; i < 4224; i += 256)
        cp16(sb + SMO_B + i * 16, reinterpret_cast<const char*>(g_WoutImg) + i * 16);
    CP_COMMIT();
    for (int idx = tid; idx < 4096; idx += 256) {
        int r = idx >> 6, c4 = (idx & 63) << 2;
        float4 x;
        if (c4 < 128) x = *reinterpret_cast<const float4*>(g_agg + (size_t)(r0 + r) * 128 + c4);
        else          x = *reinterpret_cast<const float4*>(h + (size_t)(r0 + r) * 128 + (c4 - 128));
        __half2 p0 = __floats2half2_rn(x.x, x.y);
        __half2 p1 = __floats2half2_rn(x.z, x.w);
        uint2 uh;
        uh.x = *reinterpret_cast<unsigned*>(&p0);
        uh.y = *reinterpret_cast<unsigned*>(&p1);
        *reinterpret_cast<uint2*>(smo + (uint32_t)r * 528 + c4 * 2) = uh;
    }
    CP_WAIT0();
    __syncthreads();

    float acc[2][4][4] = {};
    #pragma unroll 2
    for (int k16 = 0; k16 < 16; k16++) {
        int kb = k16 * 32;
        unsigned a4[2][4];
        #pragma unroll
        for (int mi = 0; mi < 2; mi++) {
            uint32_t ad = sb + (uint32_t)(wm * 32 + mi * 16 + arow) * 528 + kb + acolb;
            ldm_x4(a4[mi], ad);
        }
        #pragma unroll
        for (int ni = 0; ni < 4; ni++) {
            unsigned b2[2];
            uint32_t bd = sb + SMO_B + (uint32_t)(wn * 32 + ni * 8 + brow) * 528 + kb + bcolb;
            asm volatile("ldmatrix.sync.aligned.m8n8.x2.shared.b16 {%0,%1}, [%2];"
                : "=r"(b2[0]), "=r"(b2[1]) : "r"(bd));
            #pragma unroll
            for (int mi = 0; mi < 2; mi++)
                mma_f16(acc[mi][ni], a4[mi], b2);
        }
    }
    __syncthreads();

    float* Stg = reinterpret_cast<float*>(smo);
    #pragma unroll
    for (int mi = 0; mi < 2; mi++) {
        int r = wm * 32 + mi * 16 + (lane >> 2);
        #pragma unroll
        for (int ni = 0; ni < 4; ni++) {
            int c = wn * 32 + ni * 8 + (lane & 3) * 2;
            float b0 = bout[c], b1 = bout[c + 1];
            float v0 = acc[mi][ni][0] + b0, v1 = acc[mi][ni][1] + b1;
            float v2 = acc[mi][ni][2] + b0, v3 = acc[mi][ni][3] + b1;
            Stg[r * 136 + c]           = v0 > 0.f ? v0 : 0.f;
            Stg[r * 136 + c + 1]       = v1 > 0.f ? v1 : 0.f;
            Stg[(r + 8) * 136 + c]     = v2 > 0.f ? v2 : 0.f;
            Stg[(r + 8) * 136 + c + 1] = v3 > 0.f ? v3 : 0.f;
        }
    }
    __syncthreads();

    {
        int r = tid >> 2, q = tid & 3;
        float vals[32];
        float rsum = 0.f, rsq = 0.f;
        const float4* sp = reinterpret_cast<const float4*>(Stg + r * 136 + q * 32);
        #pragma unroll
        for (int u = 0; u < 8; u++) {
            float4 v = sp[u];
            vals[u * 4 + 0] = v.x; vals[u * 4 + 1] = v.y;
            vals[u * 4 + 2] = v.z; vals[u * 4 + 3] = v.w;
            rsum += v.x + v.y + v.z + v.w;
            rsq  += v.x * v.x + v.y * v.y + v.z * v.z + v.w * v.w;
        }
        #pragma unroll
        for (int m = 1; m <= 2; m <<= 1) {
            rsum += __shfl_xor_sync(0xffffffffu, rsum, m);
            rsq  += __shfl_xor_sync(0xffffffffu, rsq, m);
        }
        float mu = rsum * (1.f / 128.f);
        float var = rsq * (1.f / 128.f) - mu * mu;
        float inv = rsqrtf(var + 1e-5f);
        float* op = out + (size_t)(r0 + r) * 128 + q * 32;
        #pragma unroll
        for (int i = 0; i < 32; i++) {
            int col = q * 32 + i;
            op[i] = (vals[i] - mu) * inv * gamma[col] + beta[col];
        }
    }
}

extern "C" void kernel_launch(void* const* d_in, const int* in_sizes, int n_in,
                              void* d_out, int out_size) {
    const float* h    = (const float*)d_in[0];
    const float* f    = (const float*)d_in[1];
    const float* dt   = (const float*)d_in[2];
    const int*   dst  = (const int*)  d_in[3];
    const float* freq = (const float*)d_in[4];
    const float* tb   = (const float*)d_in[5];
    const float* Wq   = (const float*)d_in[6];
    const float* bq   = (const float*)d_in[7];
    const float* Wk   = (const float*)d_in[8];
    const float* bk   = (const float*)d_in[9];
    const float* Wv   = (const float*)d_in[10];
    const float* bv   = (const float*)d_in[11];
    const float* Wout = (const float*)d_in[12];
    const float* bout = (const float*)d_in[13];
    const float* gam  = (const float*)d_in[14];
    const float* bet  = (const float*)d_in[15];
    float* out = (float*)d_out;

    int E  = in_sizes[2];
    int Nd = in_sizes[0] / 128 - E;

    cudaFuncSetAttribute(k_qgemm, cudaFuncAttributeMaxDynamicSharedMemorySize, SMQ_TOT);
    cudaFuncSetAttribute(k_kv,    cudaFuncAttributeMaxDynamicSharedMemorySize, SM_TOT);
    cudaFuncSetAttribute(k_out,   cudaFuncAttributeMaxDynamicSharedMemorySize, SMO_TOT);

    k_prep<<<(Nd * 128 + 255) / 256, 256>>>(Wk, Wv, Wout, Wq, bq, tb, Nd);
    k_qgemm<<<Nd / 64, 256, SMQ_TOT>>>(h, Nd);
    k_kv<<<E / 64, 256, SM_TOT>>>(h, f, dt, dst, freq, tb, bk, bv, Nd, E);
    k_pass3<<<E / 32, 256>>>(dst, E);
    k_out<<<Nd / 64, 256, SMO_TOT>>>(h, bout, gam, bet, out, Nd);
}

// round 17
// speedup vs baseline: 1.1981x; 1.0649x over previous
#include <cuda_runtime.h>
#include <cuda_fp16.h>
#include <cstdint>

#define NDMAX 32768
#define EMAX  524288

__device__ float    g_Q[(size_t)NDMAX * 128];
__device__ float    g_qconst[128];
__device__ float    g_segsum[NDMAX * 8];
__device__ float    g_agg[(size_t)NDMAX * 128];        // UNNORMALIZED: sum ex*V
// fp16 W image: [chunk(3)][half(2): K/V][128 rows x 272B]
__device__ __align__(16) unsigned char g_Wimg[3 * 2 * 34816];
// fp16 Wout image: 128 rows x 528B
__device__ __align__(16) unsigned char g_WoutImg[128 * 528];
// fp16 Wq[:, :128] hi/lo image: 2 x (128 rows x 272B)
__device__ __align__(16) unsigned char g_WqImg[2 * 34816];

__device__ __forceinline__ uint32_t smem_u32(const void* p) {
    uint32_t a;
    asm("{ .reg .u64 t; cvta.to.shared.u64 t, %1; cvt.u32.u64 %0, t; }" : "=r"(a) : "l"(p));
    return a;
}
__device__ __forceinline__ void ldm_x4(unsigned* r, uint32_t addr) {
    asm volatile("ldmatrix.sync.aligned.m8n8.x4.shared.b16 {%0,%1,%2,%3}, [%4];"
        : "=r"(r[0]), "=r"(r[1]), "=r"(r[2]), "=r"(r[3]) : "r"(addr));
}
__device__ __forceinline__ void mma_f16(float* d, const unsigned* a, const unsigned* b) {
    asm volatile("mma.sync.aligned.m16n8k16.row.col.f32.f16.f16.f32 "
        "{%0,%1,%2,%3}, {%4,%5,%6,%7}, {%8,%9}, {%0,%1,%2,%3};"
        : "+f"(d[0]), "+f"(d[1]), "+f"(d[2]), "+f"(d[3])
        : "r"(a[0]), "r"(a[1]), "r"(a[2]), "r"(a[3]), "r"(b[0]), "r"(b[1]));
}
__device__ __forceinline__ void cp16(uint32_t saddr, const void* g) {
    asm volatile("cp.async.cg.shared.global [%0], [%1], 16;" :: "r"(saddr), "l"(g));
}
#define CP_COMMIT() asm volatile("cp.async.commit_group;" ::: "memory")
#define CP_WAIT0()  asm volatile("cp.async.wait_group 0;" ::: "memory")

// smem layouts (bytes)
#define SM_A    0
#define SM_B    17408
#define SM_TOT  87040
#define SM_EX   69632
#define SMO_B   33792
#define SMO_TOT 101376
#define SMQ_AHI 0
#define SMQ_ALO 17408
#define SMQ_B   34816
#define SMQ_TOT 104448

// ---------------- prep: init + all fp16 weight images + qconst ----------------
__global__ void k_prep(const float* __restrict__ Wk, const float* __restrict__ Wv,
                       const float* __restrict__ Wout,
                       const float* __restrict__ Wq, const float* __restrict__ bq,
                       const float* __restrict__ tb, int Nd) {
    int i = blockIdx.x * 256 + threadIdx.x;
    if (i < Nd * 128) g_agg[i] = 0.f;
    if (i < Nd * 8) g_segsum[i] = 0.f;
    if (i < 98304) {
        int r = i / 384, cg = i % 384;
        float w = (r < 128) ? Wk[(size_t)r * 384 + cg] : Wv[(size_t)(r - 128) * 384 + cg];
        int chunk = cg >> 7, c = cg & 127;
        int half = r >> 7, rr = r & 127;
        size_t base = (size_t)(chunk * 2 + half) * 34816 + (size_t)rr * 272 + c * 2;
        *reinterpret_cast<__half*>(g_Wimg + base) = __float2half_rn(w);
    }
    if (i < 32768) {
        int r = i >> 8, c = i & 255;
        *reinterpret_cast<__half*>(g_WoutImg + (size_t)r * 528 + c * 2) =
            __float2half_rn(Wout[(size_t)r * 256 + c]);
    }
    if (i < 16384) {
        int r = i >> 7, c = i & 127;
        float w = Wq[(size_t)r * 256 + c];
        __half hi = __float2half_rn(w);
        __half lo = __float2half_rn(w - __half2float(hi));
        size_t base = (size_t)r * 272 + c * 2;
        *reinterpret_cast<__half*>(g_WqImg + base) = hi;
        *reinterpret_cast<__half*>(g_WqImg + base + 34816) = lo;
    }
    if (blockIdx.x == 0) {
        __shared__ float ct[128];
        int t = threadIdx.x;
        if (t < 128) ct[t] = cosf(tb[t]);
        __syncthreads();
        if (t < 128) {
            float s = bq[t];
            #pragma unroll 4
            for (int j = 0; j < 128; j++) s += Wq[(size_t)t * 256 + 128 + j] * ct[j];
            g_qconst[t] = s;
        }
    }
}

// ---------------- Q GEMM via mma fp16 3-term split ----------------
__global__ __launch_bounds__(256, 2) void k_qgemm(const float* __restrict__ h, int Nd) {
    extern __shared__ char smg[];
    uint32_t sb = smem_u32(smg);
    int tid = threadIdx.x, lane = tid & 31, wid = tid >> 5;
    int wm = wid >> 2, wn = wid & 3;
    int r0 = blockIdx.x * 64;
    int arow = lane & 15, acolb = (lane >> 4) * 16;
    int bq_row = (lane & 7) + ((lane >> 4) << 3);
    int bq_k = ((lane >> 3) & 1) * 16;

    for (int i = tid; i < 4352; i += 256)
        cp16(sb + SMQ_B + i * 16, reinterpret_cast<const char*>(g_WqImg) + i * 16);
    CP_COMMIT();
    for (int idx = tid; idx < 2048; idx += 256) {
        int r = idx >> 5, c4 = (idx & 31) << 2;
        float4 x = *reinterpret_cast<const float4*>(h + (size_t)(r0 + r) * 128 + c4);
        __half h0 = __float2half_rn(x.x), h1 = __float2half_rn(x.y);
        __half h2 = __float2half_rn(x.z), h3 = __float2half_rn(x.w);
        __half l0 = __float2half_rn(x.x - __half2float(h0));
        __half l1 = __float2half_rn(x.y - __half2float(h1));
        __half l2 = __float2half_rn(x.z - __half2float(h2));
        __half l3 = __float2half_rn(x.w - __half2float(h3));
        uint2 uh, ul;
        uh.x = (uint32_t)__half_as_ushort(h0) | ((uint32_t)__half_as_ushort(h1) << 16);
        uh.y = (uint32_t)__half_as_ushort(h2) | ((uint32_t)__half_as_ushort(h3) << 16);
        ul.x = (uint32_t)__half_as_ushort(l0) | ((uint32_t)__half_as_ushort(l1) << 16);
        ul.y = (uint32_t)__half_as_ushort(l2) | ((uint32_t)__half_as_ushort(l3) << 16);
        uint32_t off = (uint32_t)r * 272 + c4 * 2;
        *reinterpret_cast<uint2*>(smg + SMQ_AHI + off) = uh;
        *reinterpret_cast<uint2*>(smg + SMQ_ALO + off) = ul;
    }
    CP_WAIT0();
    __syncthreads();

    float acc[2][4][4] = {};
    #pragma unroll 2
    for (int k16 = 0; k16 < 8; k16++) {
        int kb = k16 * 32;
        unsigned ahi[2][4], alo[2][4];
        #pragma unroll
        for (int mi = 0; mi < 2; mi++) {
            uint32_t ad = sb + (uint32_t)(wm * 32 + mi * 16 + arow) * 272 + kb + acolb;
            ldm_x4(ahi[mi], ad + SMQ_AHI);
            ldm_x4(alo[mi], ad + SMQ_ALO);
        }
        #pragma unroll
        for (int p = 0; p < 2; p++) {
            unsigned bhi[4], blo[4];
            uint32_t bd = sb + SMQ_B + (uint32_t)(wn * 32 + p * 16 + bq_row) * 272 + kb + bq_k;
            ldm_x4(bhi, bd);
            ldm_x4(blo, bd + 34816);
            #pragma unroll
            for (int mi = 0; mi < 2; mi++) {
                mma_f16(acc[mi][2 * p],     ahi[mi], bhi);
                mma_f16(acc[mi][2 * p],     ahi[mi], blo);
                mma_f16(acc[mi][2 * p],     alo[mi], bhi);
                mma_f16(acc[mi][2 * p + 1], ahi[mi], bhi + 2);
                mma_f16(acc[mi][2 * p + 1], ahi[mi], blo + 2);
                mma_f16(acc[mi][2 * p + 1], alo[mi], bhi + 2);
            }
        }
    }
    __syncthreads();

    float* Stg = reinterpret_cast<float*>(smg);
    #pragma unroll
    for (int mi = 0; mi < 2; mi++) {
        int r = wm * 32 + mi * 16 + (lane >> 2);
        #pragma unroll
        for (int ni = 0; ni < 4; ni++) {
            int c = wn * 32 + ni * 8 + (lane & 3) * 2;
            Stg[r * 136 + c]           = acc[mi][ni][0];
            Stg[r * 136 + c + 1]       = acc[mi][ni][1];
            Stg[(r + 8) * 136 + c]     = acc[mi][ni][2];
            Stg[(r + 8) * 136 + c + 1] = acc[mi][ni][3];
        }
    }
    __syncthreads();
    for (int idx = tid; idx < 2048; idx += 256) {
        int r = idx >> 5, c4 = (idx & 31) << 2;
        float4 v = *reinterpret_cast<const float4*>(Stg + r * 136 + c4);
        v.x += g_qconst[c4 + 0]; v.y += g_qconst[c4 + 1];
        v.z += g_qconst[c4 + 2]; v.w += g_qconst[c4 + 3];
        *reinterpret_cast<float4*>(g_Q + (size_t)(r0 + r) * 128 + c4) = v;
    }
}

// ---------------- KV GEMM: fp16 1-term + fused logits + direct ex*V aggregation ----------------
__global__ __launch_bounds__(256, 2) void k_kv(
    const float* __restrict__ h, const float* __restrict__ f,
    const float* __restrict__ dt, const int* __restrict__ dst,
    const float* __restrict__ freq, const float* __restrict__ tb,
    const float* __restrict__ bk, const float* __restrict__ bv,
    int Nd, int E)
{
    extern __shared__ char smc[];
    uint32_t sb = smem_u32(smc);
    int tid = threadIdx.x, lane = tid & 31, wid = tid >> 5;
    int wm = wid >> 2, wn = wid & 3;
    int e0 = blockIdx.x * 64;

    int arow = lane & 15, acolb = (lane >> 4) * 16;
    int bq_row = (lane & 7) + ((lane >> 4) << 3);
    int bq_k = ((lane >> 3) & 1) * 16;

    uint32_t bwbase = sb + SM_B + (uint32_t)(wn >> 1) * 34816 + (uint32_t)((wn & 1) * 64) * 272;

    float acc[2][8][4] = {};

    for (int chunk = 0; chunk < 3; chunk++) {
        __syncthreads();
        {
            const char* src = reinterpret_cast<const char*>(g_Wimg) + (size_t)chunk * 69632;
            for (int i = tid; i < 4352; i += 256)
                cp16(sb + SM_B + i * 16, src + i * 16);
            CP_COMMIT();
        }
        for (int idx = tid; idx < 2048; idx += 256) {
            int e = idx >> 5, k4 = (idx & 31) << 2;
            float4 x;
            if (chunk == 0) {
                x = *reinterpret_cast<const float4*>(h + (size_t)(Nd + e0 + e) * 128 + k4);
            } else if (chunk == 1) {
                x = *reinterpret_cast<const float4*>(f + (size_t)(e0 + e) * 128 + k4);
            } else {
                float dtv = dt[e0 + e];
                x.x = __cosf(fmaf(dtv, freq[k4 + 0], tb[k4 + 0]));
                x.y = __cosf(fmaf(dtv, freq[k4 + 1], tb[k4 + 1]));
                x.z = __cosf(fmaf(dtv, freq[k4 + 2], tb[k4 + 2]));
                x.w = __cosf(fmaf(dtv, freq[k4 + 3], tb[k4 + 3]));
            }
            __half2 p0 = __floats2half2_rn(x.x, x.y);
            __half2 p1 = __floats2half2_rn(x.z, x.w);
            uint2 uh;
            uh.x = *reinterpret_cast<unsigned*>(&p0);
            uh.y = *reinterpret_cast<unsigned*>(&p1);
            uint32_t off = (uint32_t)e * 272 + k4 * 2;
            *reinterpret_cast<uint2*>(smc + SM_A + off) = uh;
        }
        CP_WAIT0();
        __syncthreads();

        #pragma unroll 2
        for (int k16 = 0; k16 < 8; k16++) {
            int kb = k16 * 32;
            unsigned a4[2][4];
            #pragma unroll
            for (int mi = 0; mi < 2; mi++) {
                uint32_t ad = sb + SM_A + (uint32_t)(wm * 32 + mi * 16 + arow) * 272 + kb + acolb;
                ldm_x4(a4[mi], ad);
            }
            #pragma unroll
            for (int p = 0; p < 4; p++) {
                unsigned b4[4];
                uint32_t bd = bwbase + (uint32_t)(p * 16 + bq_row) * 272 + kb + bq_k;
                ldm_x4(b4, bd);
                #pragma unroll
                for (int mi = 0; mi < 2; mi++) {
                    mma_f16(acc[mi][2 * p],     a4[mi], b4);
                    mma_f16(acc[mi][2 * p + 1], a4[mi], b4 + 2);
                }
            }
        }
    }
    __syncthreads();

    float* Ks  = reinterpret_cast<float*>(smc);
    float* Vs  = reinterpret_cast<float*>(smc + 34816);
    float* exS = reinterpret_cast<float*>(smc + SM_EX);   // 64 x 8 floats
    {
        float* stage = (wn < 2) ? Ks : Vs;
        const float* bias = (wn < 2) ? bk : bv;
        int cbase = (wn & 1) * 64;
        #pragma unroll
        for (int mi = 0; mi < 2; mi++) {
            int r = wm * 32 + mi * 16 + (lane >> 2);
            #pragma unroll
            for (int ni = 0; ni < 8; ni++) {
                int c = cbase + ni * 8 + (lane & 3) * 2;
                float b0 = bias[c], b1 = bias[c + 1];
                stage[r * 136 + c]           = acc[mi][ni][0] + b0;
                stage[r * 136 + c + 1]       = acc[mi][ni][1] + b1;
                stage[(r + 8) * 136 + c]     = acc[mi][ni][2] + b0;
                stage[(r + 8) * 136 + c + 1] = acc[mi][ni][3] + b1;
            }
        }
    }
    __syncthreads();

    // logits -> exp, stash in smem, accumulate segsum
    for (int t = tid; t < 512; t += 256) {
        int e = t >> 3, hh = t & 7;
        int d = dst[e0 + e];
        const float4* qp = reinterpret_cast<const float4*>(g_Q + (size_t)d * 128 + hh * 16);
        const float4* kp = reinterpret_cast<const float4*>(Ks + e * 136 + hh * 16);
        float s = 0.f;
        #pragma unroll
        for (int u = 0; u < 4; u++) {
            float4 q = qp[u], kv = kp[u];
            s += q.x * kv.x + q.y * kv.y + q.z * kv.z + q.w * kv.w;
        }
        float lg = (s >= 0.f) ? s : 0.2f * s;
        float ex = __expf(fminf(lg, 60.f));
        exS[e * 8 + hh] = ex;
        atomicAdd(&g_segsum[d * 8 + hh], ex);
    }
    __syncthreads();

    // direct unnormalized aggregation: agg[d] += ex * V
    for (int idx = tid; idx < 2048; idx += 256) {
        int e = idx >> 5, u2 = idx & 31;
        int d = dst[e0 + e];
        float ex = exS[e * 8 + (u2 >> 2)];
        const float4 v = *reinterpret_cast<const float4*>(Vs + e * 136 + u2 * 4);
        float* ap = g_agg + (size_t)d * 128 + u2 * 4;
        asm volatile("red.global.add.v4.f32 [%0], {%1, %2, %3, %4};"
            :: "l"(ap), "f"(v.x * ex), "f"(v.y * ex), "f"(v.z * ex), "f"(v.w * ex)
            : "memory");
    }
}

// ---------------- out GEMM via mma fp16 + segsum normalization + fused LN ----------------
__global__ __launch_bounds__(256, 2) void k_out(
    const float* __restrict__ h, const float* __restrict__ bout,
    const float* __restrict__ gamma, const float* __restrict__ beta,
    float* __restrict__ out, int Nd)
{
    extern __shared__ char smo[];
    uint32_t sb = smem_u32(smo);
    int tid = threadIdx.x, lane = tid & 31, wid = tid >> 5;
    int wm = wid >> 2, wn = wid & 3;
    int r0 = blockIdx.x * 64;

    int arow = lane & 15, acolb = (lane >> 4) * 16;
    int brow = lane & 7,  bcolb = ((lane >> 3) & 1) * 16;

    for (int i = tid; i < 4224; i += 256)
        cp16(sb + SMO_B + i * 16, reinterpret_cast<const char*>(g_WoutImg) + i * 16);
    CP_COMMIT();
    for (int idx = tid; idx < 4096; idx += 256) {
        int r = idx >> 6, c4 = (idx & 63) << 2;
        float4 x;
        if (c4 < 128) {
            x = *reinterpret_cast<const float4*>(g_agg + (size_t)(r0 + r) * 128 + c4);
            float ss = g_segsum[(r0 + r) * 8 + (c4 >> 4)];
            float inv = (ss > 0.f) ? __fdividef(1.f, ss) : 0.f;
            x.x *= inv; x.y *= inv; x.z *= inv; x.w *= inv;
        } else {
            x = *reinterpret_cast<const float4*>(h + (size_t)(r0 + r) * 128 + (c4 - 128));
        }
        __half2 p0 = __floats2half2_rn(x.x, x.y);
        __half2 p1 = __floats2half2_rn(x.z, x.w);
        uint2 uh;
        uh.x = *reinterpret_cast<unsigned*>(&p0);
        uh.y = *reinterpret_cast<unsigned*>(&p1);
        *reinterpret_cast<uint2*>(smo + (uint32_t)r * 528 + c4 * 2) = uh;
    }
    CP_WAIT0();
    __syncthreads();

    float acc[2][4][4] = {};
    #pragma unroll 2
    for (int k16 = 0; k16 < 16; k16++) {
        int kb = k16 * 32;
        unsigned a4[2][4];
        #pragma unroll
        for (int mi = 0; mi < 2; mi++) {
            uint32_t ad = sb + (uint32_t)(wm * 32 + mi * 16 + arow) * 528 + kb + acolb;
            ldm_x4(a4[mi], ad);
        }
        #pragma unroll
        for (int ni = 0; ni < 4; ni++) {
            unsigned b2[2];
            uint32_t bd = sb + SMO_B + (uint32_t)(wn * 32 + ni * 8 + brow) * 528 + kb + bcolb;
            asm volatile("ldmatrix.sync.aligned.m8n8.x2.shared.b16 {%0,%1}, [%2];"
                : "=r"(b2[0]), "=r"(b2[1]) : "r"(bd));
            #pragma unroll
            for (int mi = 0; mi < 2; mi++)
                mma_f16(acc[mi][ni], a4[mi], b2);
        }
    }
    __syncthreads();

    float* Stg = reinterpret_cast<float*>(smo);
    #pragma unroll
    for (int mi = 0; mi < 2; mi++) {
        int r = wm * 32 + mi * 16 + (lane >> 2);
        #pragma unroll
        for (int ni = 0; ni < 4; ni++) {
            int c = wn * 32 + ni * 8 + (lane & 3) * 2;
            float b0 = bout[c], b1 = bout[c + 1];
            float v0 = acc[mi][ni][0] + b0, v1 = acc[mi][ni][1] + b1;
            float v2 = acc[mi][ni][2] + b0, v3 = acc[mi][ni][3] + b1;
            Stg[r * 136 + c]           = v0 > 0.f ? v0 : 0.f;
            Stg[r * 136 + c + 1]       = v1 > 0.f ? v1 : 0.f;
            Stg[(r + 8) * 136 + c]     = v2 > 0.f ? v2 : 0.f;
            Stg[(r + 8) * 136 + c + 1] = v3 > 0.f ? v3 : 0.f;
        }
    }
    __syncthreads();

    {
        int r = tid >> 2, q = tid & 3;
        float vals[32];
        float rsum = 0.f, rsq = 0.f;
        const float4* sp = reinterpret_cast<const float4*>(Stg + r * 136 + q * 32);
        #pragma unroll
        for (int u = 0; u < 8; u++) {
            float4 v = sp[u];
            vals[u * 4 + 0] = v.x; vals[u * 4 + 1] = v.y;
            vals[u * 4 + 2] = v.z; vals[u * 4 + 3] = v.w;
            rsum += v.x + v.y + v.z + v.w;
            rsq  += v.x * v.x + v.y * v.y + v.z * v.z + v.w * v.w;
        }
        #pragma unroll
        for (int m = 1; m <= 2; m <<= 1) {
            rsum += __shfl_xor_sync(0xffffffffu, rsum, m);
            rsq  += __shfl_xor_sync(0xffffffffu, rsq, m);
        }
        float mu = rsum * (1.f / 128.f);
        float var = rsq * (1.f / 128.f) - mu * mu;
        float inv = rsqrtf(var + 1e-5f);
        float* op = out + (size_t)(r0 + r) * 128 + q * 32;
        #pragma unroll
        for (int i = 0; i < 32; i++) {
            int col = q * 32 + i;
            op[i] = (vals[i] - mu) * inv * gamma[col] + beta[col];
        }
    }
}

extern "C" void kernel_launch(void* const* d_in, const int* in_sizes, int n_in,
                              void* d_out, int out_size) {
    const float* h    = (const float*)d_in[0];
    const float* f    = (const float*)d_in[1];
    const float* dt   = (const float*)d_in[2];
    const int*   dst  = (const int*)  d_in[3];
    const float* freq = (const float*)d_in[4];
    const float* tb   = (const float*)d_in[5];
    const float* Wq   = (const float*)d_in[6];
    const float* bq   = (const float*)d_in[7];
    const float* Wk   = (const float*)d_in[8];
    const float* bk   = (const float*)d_in[9];
    const float* Wv   = (const float*)d_in[10];
    const float* bv   = (const float*)d_in[11];
    const float* Wout = (const float*)d_in[12];
    const float* bout = (const float*)d_in[13];
    const float* gam  = (const float*)d_in[14];
    const float* bet  = (const float*)d_in[15];
    float* out = (float*)d_out;

    int E  = in_sizes[2];
    int Nd = in_sizes[0] / 128 - E;

    cudaFuncSetAttribute(k_qgemm, cudaFuncAttributeMaxDynamicSharedMemorySize, SMQ_TOT);
    cudaFuncSetAttribute(k_kv,    cudaFuncAttributeMaxDynamicSharedMemorySize, SM_TOT);
    cudaFuncSetAttribute(k_out,   cudaFuncAttributeMaxDynamicSharedMemorySize, SMO_TOT);

    k_prep<<<(Nd * 128 + 255) / 256, 256>>>(Wk, Wv, Wout, Wq, bq, tb, Nd);
    k_qgemm<<<Nd / 64, 256, SMQ_TOT>>>(h, Nd);
    k_kv<<<E / 64, 256, SM_TOT>>>(h, f, dt, dst, freq, tb, bk, bv, Nd, E);
    k_out<<<Nd / 64, 256, SMO_TOT>>>(h, bout, gam, bet, out, Nd);
}